// round 15
// baseline (speedup 1.0000x reference)
#include <cuda_runtime.h>
#include <cuda_bf16.h>
#include <math.h>
#include <cstdint>

#define EPS 1e-5f

// Problem dims
#define BSZ   1024
#define EDIM  200
#define NE_   50000
#define OCFW  288     // 32*9
#define FCIN  6144    // 32*192
#define SPLITK 16

#define KP2   416     // K pad for GEMM2 (E+R=400 -> 13*32)
#define KPS   224     // K pad for 200-dim mma.sync operands (7*32)
#define KP4   208     // K pad for GEMM4 operands (13*16)
#define LDS_  40      // smem row stride bf16 (80B) - conflict-free ldmatrix
#define STAGE_BYTES (2 * 128 * LDS_ * 2)   // A+B per stage = 20480
#define SMEM_TC (3 * STAGE_BYTES)          // 61440

// GEMM4 (A-resident, 128x128 CTA tile) smem layout, 3 B stages (R12-proven)
#define A4_STR 232
#define SM4A   (128 * A4_STR * 2)           // 59392
#define SM4B_STAGE (128 * LDS_ * 2)         // 10240
#define SM4_TOTAL (SM4A + 3 * SM4B_STAGE)   // 90112

// prep kernel block ranges (R8-proven all-in-one)
#define NB_ENT    ((NE_ * 52 + 255) / 256)          // 10157
#define NB_W1T    ((EDIM * KP2 + 255) / 256)        // 325
#define NB_FC1T   ((OCFW * KPS + 255) / 256)        // 252
#define NB_FCT    ((FCIN / 32) * ((EDIM + 31) / 32))// 1344
#define NB_GATHER BSZ
#define OFF_W1T    NB_ENT
#define OFF_FC1T   (OFF_W1T + NB_W1T)
#define OFF_FCT    (OFF_FC1T + NB_FC1T)
#define OFF_GATHER (OFF_FCT + NB_FCT)
#define NB_PREP    (OFF_GATHER + NB_GATHER)

typedef unsigned unt;

// ---------------- scratch ----------------------------------------------------
__device__ __align__(16) __nv_bfloat16 g_cat_bf [BSZ * KP2];
__device__ __align__(16) __nv_bfloat16 g_rg_bf  [BSZ * KPS];
__device__ float g_x   [BSZ * EDIM];
__device__ float g_k   [BSZ * OCFW];
__device__ __align__(16) __nv_bfloat16 g_flat_bf[BSZ * FCIN];
__device__ float g_part[SPLITK * BSZ * EDIM];
__device__ __align__(16) __nv_bfloat16 g_h_bf [BSZ * KP4];
__device__ __align__(16) __nv_bfloat16 g_ent_bf[(size_t)NE_ * KP4];  // 20.8MB
__device__ __align__(16) __nv_bfloat16 g_w1t [EDIM * KP2];
__device__ __align__(16) __nv_bfloat16 g_fc1t[OCFW * KPS];
__device__ __align__(16) __nv_bfloat16 g_fct [EDIM * FCIN];

// ---------------- asm helpers --------------------------------------------------
__device__ __forceinline__ unt smem_u32(const void* p) {
    unt a;
    asm("{ .reg .u64 t; cvta.to.shared.u64 t, %1; cvt.u32.u64 %0, t; }"
        : "=r"(a) : "l"(p));
    return a;
}
__device__ __forceinline__ void ldsm_x4(unt* r, const __nv_bfloat16* p) {
    unt addr = smem_u32(p);
    asm volatile("ldmatrix.sync.aligned.m8n8.x4.shared.b16 {%0,%1,%2,%3}, [%4];"
                 : "=r"(r[0]), "=r"(r[1]), "=r"(r[2]), "=r"(r[3]) : "r"(addr));
}
__device__ __forceinline__ void mma_bf16(float* c, const unt* a, const unt* b) {
    asm volatile("mma.sync.aligned.m16n8k16.row.col.f32.bf16.bf16.f32 "
                 "{%0,%1,%2,%3},{%4,%5,%6,%7},{%8,%9},{%0,%1,%2,%3};"
                 : "+f"(c[0]), "+f"(c[1]), "+f"(c[2]), "+f"(c[3])
                 : "r"(a[0]), "r"(a[1]), "r"(a[2]), "r"(a[3]),
                   "r"(b[0]), "r"(b[1]));
}
__device__ __forceinline__ void cp16p(__nv_bfloat16* dst, const __nv_bfloat16* src, bool pred) {
    unt d = smem_u32(dst);
    int sz = pred ? 16 : 0;
    asm volatile("cp.async.cg.shared.global [%0], [%1], 16, %2;"
                 :: "r"(d), "l"(src), "r"(sz));
}
#define CP_COMMIT() asm volatile("cp.async.commit_group;")
#define CP_WAIT1()  asm volatile("cp.async.wait_group 1;")

// streaming (evict-first) 8B store: keeps L2 for the entity table
__device__ __forceinline__ void st_cs_f2(float* p, float x, float y) {
    float2 v = make_float2(x, y);
    asm volatile("st.global.cs.v2.f32 [%0], {%1, %2};"
                 :: "l"(p), "f"(v.x), "f"(v.y) : "memory");
}
// streaming (evict-first) load
__device__ __forceinline__ float ld_cs_f(const float* p) {
    float v;
    asm volatile("ld.global.cs.f32 %0, [%1];" : "=f"(v) : "l"(p));
    return v;
}

__device__ __forceinline__ float sigf(float x) {
    float e, r;
    asm("ex2.approx.f32 %0, %1;" : "=f"(e) : "f"(-1.44269504f * x));
    asm("rcp.approx.f32 %0, %1;" : "=f"(r) : "f"(1.f + e));
    return r;
}

// ---------------- prep: all converters + gather in one launch (R8) --------------
__global__ __launch_bounds__(256)
void prep_kernel(const float* __restrict__ ent, const float* __restrict__ rel,
                 const float* __restrict__ W1_w, const float* __restrict__ fc1_w,
                 const float* __restrict__ fc_w,
                 const int* __restrict__ e_s, const int* __restrict__ q_s,
                 const int* __restrict__ e_c) {
    __shared__ float tile[32][33];
    const int bid = blockIdx.x;
    const int t = threadIdx.x;

    if (bid < NB_ENT) {
        int idx = bid * 256 + t;
        if (idx < NE_ * 52) {
            int r = idx / 52, q = idx % 52;
            float4 v = make_float4(0.f, 0.f, 0.f, 0.f);
            if (q < 50) v = *(const float4*)(ent + (size_t)r * EDIM + q * 4);
            __nv_bfloat162 lo = __floats2bfloat162_rn(v.x, v.y);
            __nv_bfloat162 hi = __floats2bfloat162_rn(v.z, v.w);
            uint2 pk;
            pk.x = *(unt*)&lo; pk.y = *(unt*)&hi;
            *(uint2*)(g_ent_bf + (size_t)r * KP4 + q * 4) = pk;
        }
    } else if (bid < OFF_FC1T) {
        int idx = (bid - OFF_W1T) * 256 + t;
        if (idx < EDIM * KP2) {
            int n = idx / KP2, c = idx % KP2;
            float v = (c < 2 * EDIM) ? W1_w[c * EDIM + n] : 0.f;
            g_w1t[idx] = __float2bfloat16(v);
        }
    } else if (bid < OFF_FCT) {
        int idx = (bid - OFF_FC1T) * 256 + t;
        if (idx < OCFW * KPS) {
            int n = idx / KPS, c = idx % KPS;
            float v = (c < EDIM) ? fc1_w[c * OCFW + n] : 0.f;
            g_fc1t[idx] = __float2bfloat16(v);
        }
    } else if (bid < OFF_GATHER) {
        int b2 = bid - OFF_FCT;
        int bx = b2 % (FCIN / 32);
        int by = b2 / (FCIN / 32);
        int tx = t & 31, ty = t >> 5;
        int cbase = bx * 32;
        int nbase = by * 32;
#pragma unroll
        for (int j = 0; j < 4; j++) {
            int cc = cbase + ty + j * 8;
            int nn = nbase + tx;
            tile[ty + j * 8][tx] = (nn < EDIM) ? fc_w[(size_t)cc * EDIM + nn] : 0.f;
        }
        __syncthreads();
#pragma unroll
        for (int j = 0; j < 4; j++) {
            int nn = nbase + ty + j * 8;
            int cc = cbase + tx;
            if (nn < EDIM)
                g_fct[(size_t)nn * FCIN + cc] = __float2bfloat16(tile[tx][ty + j * 8]);
        }
    } else {
        int b = bid - OFF_GATHER;
        int s = e_s[b], c = e_c[b], q = q_s[b];
        for (int j = t; j < KP2; j += 256) {
            float cv = 0.f;
            if (j < EDIM)          cv = ent[(size_t)s * EDIM + j];
            else if (j < 2 * EDIM) cv = ent[(size_t)c * EDIM + (j - EDIM)];
            g_cat_bf[b * KP2 + j] = __float2bfloat16(cv);
        }
        for (int j = t; j < KPS; j += 256) {
            float rv = (j < EDIM) ? rel[(size_t)q * EDIM + j] : 0.f;
            g_rg_bf[b * KPS + j] = __float2bfloat16(rv);
        }
    }
}

// ---------------- shared mma.sync GEMM body (runtime mode) ---------------------
__device__ __forceinline__ void gemm_body(
    int mode, const __nv_bfloat16* A, const __nv_bfloat16* B, float* C,
    int N, int kp, int kiters, int ksteps, int ldc,
    const float* bias, const float* p0, const float* p1,
    const float* p2, const float* p3,
    int m0, int n0, int kbase, size_t rowbase, char* sm) {
    const int tid = threadIdx.x;

    auto load_stage = [&](int kb, int stage) {
        __nv_bfloat16* As = (__nv_bfloat16*)(sm + stage * STAGE_BYTES);
        __nv_bfloat16* Bs = As + 128 * LDS_;
#pragma unroll
        for (int j = 0; j < 2; j++) {
            int i = tid + j * 256;
            int r = i >> 2, c = (i & 3) * 8;
            cp16p(As + r * LDS_ + c, A + (size_t)(m0 + r) * kp + kb * 32 + c, true);
            bool pn = (n0 + r) < N;
            const __nv_bfloat16* bs = pn ? (B + (size_t)(n0 + r) * kp + kb * 32 + c) : B;
            cp16p(Bs + r * LDS_ + c, bs, pn);
        }
    };

    load_stage(kbase + 0, 0); CP_COMMIT();
    load_stage(kbase + 1, 1); CP_COMMIT();

    const int lane = tid & 31, wid = tid >> 5;
    const int wm = (wid & 3) * 32;
    const int wn = (wid >> 2) * 64;

    float acc[2][8][4];
#pragma unroll
    for (int i = 0; i < 2; i++)
#pragma unroll
        for (int j = 0; j < 8; j++)
#pragma unroll
            for (int l = 0; l < 4; l++) acc[i][j][l] = 0.f;

    for (int kb = 0; kb < kiters; kb++) {
        CP_WAIT1();
        __syncthreads();
        if (kb + 2 < kiters) load_stage(kbase + kb + 2, (kb + 2) % 3);
        CP_COMMIT();
        int smax = ksteps - 2 * kb;
        if (smax > 2) smax = 2;
        const __nv_bfloat16* As = (const __nv_bfloat16*)(sm + (kb % 3) * STAGE_BYTES);
        const __nv_bfloat16* Bs = As + 128 * LDS_;
#pragma unroll
        for (int ks = 0; ks < 2; ks++) {
            if (ks >= smax) break;
            unt a[2][4];
#pragma unroll
            for (int mi = 0; mi < 2; mi++) {
                int row = wm + mi * 16 + (lane & 15);
                ldsm_x4(a[mi], As + row * LDS_ + ks * 16 + (lane >> 4) * 8);
            }
            unt b[8][2];
#pragma unroll
            for (int nj = 0; nj < 4; nj++) {
                int row = wn + nj * 16 + ((lane >> 4) & 1) * 8 + (lane & 7);
                int ko  = ks * 16 + ((lane >> 3) & 1) * 8;
                unt tt[4];
                ldsm_x4(tt, Bs + row * LDS_ + ko);
                b[2 * nj][0] = tt[0]; b[2 * nj][1] = tt[1];
                b[2 * nj + 1][0] = tt[2]; b[2 * nj + 1][1] = tt[3];
            }
#pragma unroll
            for (int mi = 0; mi < 2; mi++)
#pragma unroll
                for (int ni = 0; ni < 8; ni++)
                    mma_bf16(acc[mi][ni], a[mi], b[ni]);
        }
        __syncthreads();
    }

    float sc0 = 1.f, sm0 = 0.f, sb0 = 0.f;
    if (mode == 0) {
        sc0 = p0[0] * rsqrtf(p1[0] + EPS);
        sm0 = p2[0];
        sb0 = p3[0];
    }
#pragma unroll
    for (int mi = 0; mi < 2; mi++) {
#pragma unroll
        for (int ni = 0; ni < 8; ni++) {
            int row = m0 + wm + mi * 16 + (lane >> 2);
            int col = n0 + wn + ni * 8 + (lane & 3) * 2;
            if (col < N) {
                float v0 = acc[mi][ni][0];
                float v1 = acc[mi][ni][1];
                float v2 = acc[mi][ni][2];
                float v3 = acc[mi][ni][3];
                if (mode != 2) {
                    float bb0 = bias[col], bb1 = bias[col + 1];
                    v0 += bb0; v1 += bb1; v2 += bb0; v3 += bb1;
                }
                if (mode == 0) {
                    v0 = (v0 - sm0) * sc0 + sb0; v1 = (v1 - sm0) * sc0 + sb0;
                    v2 = (v2 - sm0) * sc0 + sb0; v3 = (v3 - sm0) * sc0 + sb0;
                }
                if (mode == 2) {
                    st_cs_f2(C + (rowbase + row) * (size_t)ldc + col,     v0, v1);
                    st_cs_f2(C + (rowbase + row + 8) * (size_t)ldc + col, v2, v3);
                } else {
                    *(float2*)(C + (rowbase + row) * (size_t)ldc + col)     = make_float2(v0, v1);
                    *(float2*)(C + (rowbase + row + 8) * (size_t)ldc + col) = make_float2(v2, v3);
                }
            }
        }
    }
}

// ---------------- GEMM2 + GEMM3 fused into one launch (R8) ----------------------
__global__ __launch_bounds__(256, 2)
void gemm23_kernel(const float* __restrict__ W1_b,
                   const float* __restrict__ bn0_g, const float* __restrict__ bn0_v,
                   const float* __restrict__ bn0_m, const float* __restrict__ bn0_b,
                   const float* __restrict__ fc1_b) {
    extern __shared__ char sm[];
    const int bx = blockIdx.x;
    const int m0 = blockIdx.y * 128;
    if (bx < 2) {
        gemm_body(0, g_cat_bf, g_w1t, g_x, EDIM, KP2, KP2 / 32, 25, EDIM,
                  W1_b, bn0_g, bn0_v, bn0_m, bn0_b, m0, bx * 128, 0, 0, sm);
    } else {
        gemm_body(1, g_rg_bf, g_fc1t, g_k, OCFW, KPS, KPS / 32, 13, OCFW,
                  fc1_b, nullptr, nullptr, nullptr, nullptr,
                  m0, (bx - 2) * 128, 0, 0, sm);
    }
}

// ---------------- GEMM5: split-K partials (SPLITK=16, measured better) ----------
__global__ __launch_bounds__(256, 2)
void gemm5_kernel() {
    extern __shared__ char sm[];
    const int kiters = FCIN / 32 / SPLITK;   // 12
    gemm_body(2, g_flat_bf, g_fct, g_part, EDIM, FCIN, kiters, 2 * kiters, EDIM,
              nullptr, nullptr, nullptr, nullptr, nullptr,
              blockIdx.y * 128, blockIdx.x * 128, blockIdx.z * kiters,
              (size_t)blockIdx.z * BSZ, sm);
}

// -------- GEMM4: 128x128 CTA tile, A-resident, 3-stage B, streaming stores ------
// grid is (x = 8 m-stripes, y = 391 n-tiles): x-fastest dispatch makes all 8
// reads of each B region happen within one wave window (tight L2 temporal reuse).
__global__ __launch_bounds__(256, 2)
void gemm4_ms(const float* __restrict__ bias, float* __restrict__ out) {
    extern __shared__ char sm[];
    __nv_bfloat16* Asm = (__nv_bfloat16*)sm;
    const int tid = threadIdx.x;
    const int m0 = blockIdx.x * 128;          // 8 m-stripes, fastest dim
    const int n0 = blockIdx.y * 128;          // 391 n-tiles

    for (int i = tid; i < 3328; i += 256) {
        int r = i / 26, c = (i % 26) * 8;
        cp16p(Asm + r * A4_STR + c, g_h_bf + (size_t)(m0 + r) * KP4 + c, true);
    }
    CP_COMMIT();

    auto loadB = [&](int kb, int st) {
        __nv_bfloat16* Bs = (__nv_bfloat16*)(sm + SM4A + st * SM4B_STAGE);
#pragma unroll
        for (int j = 0; j < 2; j++) {
            int i = tid + j * 256;
            int r = i >> 2, c = (i & 3) * 8;
            bool pv = ((n0 + r) < NE_) && (kb * 32 + c < KP4);
            const __nv_bfloat16* src =
                pv ? (g_ent_bf + (size_t)(n0 + r) * KP4 + kb * 32 + c) : g_ent_bf;
            cp16p(Bs + r * LDS_ + c, src, pv);
        }
    };
    loadB(0, 0); CP_COMMIT();
    loadB(1, 1); CP_COMMIT();

    const int lane = tid & 31, wid = tid >> 5;
    const int wm = (wid & 3) * 32;
    const int wn = (wid >> 2) * 64;

    float acc[2][8][4];
#pragma unroll
    for (int i = 0; i < 2; i++)
#pragma unroll
        for (int j = 0; j < 8; j++)
#pragma unroll
            for (int l = 0; l < 4; l++) acc[i][j][l] = 0.f;

#pragma unroll
    for (int kb = 0; kb < 7; kb++) {
        CP_WAIT1();
        __syncthreads();
        if (kb + 2 < 7) loadB(kb + 2, (kb + 2) % 3);
        CP_COMMIT();
        const __nv_bfloat16* Bs =
            (const __nv_bfloat16*)(sm + SM4A + (kb % 3) * SM4B_STAGE);
        int smax = (kb == 6) ? 1 : 2;     // k 208..224 is pad
#pragma unroll
        for (int ks = 0; ks < 2; ks++) {
            if (ks >= smax) break;
            unt a[2][4];
#pragma unroll
            for (int mi = 0; mi < 2; mi++) {
                int row = wm + mi * 16 + (lane & 15);
                ldsm_x4(a[mi], Asm + row * A4_STR + kb * 32 + ks * 16 + (lane >> 4) * 8);
            }
            unt b[8][2];
#pragma unroll
            for (int nj = 0; nj < 4; nj++) {
                int row = wn + nj * 16 + ((lane >> 4) & 1) * 8 + (lane & 7);
                int ko  = ks * 16 + ((lane >> 3) & 1) * 8;
                unt tt[4];
                ldsm_x4(tt, Bs + row * LDS_ + ko);
                b[2 * nj][0] = tt[0]; b[2 * nj][1] = tt[1];
                b[2 * nj + 1][0] = tt[2]; b[2 * nj + 1][1] = tt[3];
            }
#pragma unroll
            for (int mi = 0; mi < 2; mi++)
#pragma unroll
                for (int ni = 0; ni < 8; ni++)
                    mma_bf16(acc[mi][ni], a[mi], b[ni]);
        }
        __syncthreads();
    }

    // epilogue: + bias, sigmoid; STREAMING stores (keep entity table in L2)
#pragma unroll
    for (int mi = 0; mi < 2; mi++) {
#pragma unroll
        for (int ni = 0; ni < 8; ni++) {
            int row = m0 + wm + mi * 16 + (lane >> 2);
            int col = n0 + wn + ni * 8 + (lane & 3) * 2;
            if (col < NE_) {
                float bb0 = bias[col], bb1 = bias[col + 1];
                float v0 = sigf(acc[mi][ni][0] + bb0);
                float v1 = sigf(acc[mi][ni][1] + bb1);
                float v2 = sigf(acc[mi][ni][2] + bb0);
                float v3 = sigf(acc[mi][ni][3] + bb1);
                st_cs_f2(out + (size_t)row * NE_ + col,       v0, v1);
                st_cs_f2(out + (size_t)(row + 8) * NE_ + col, v2, v3);
            }
        }
    }
}

// ---------------- per-sample dynamic conv + bn1 -> bf16 flat (R8, 192 thr) ------
__global__ void conv_kernel(const float* __restrict__ bn1_g,
                            const float* __restrict__ bn1_b,
                            const float* __restrict__ bn1_m,
                            const float* __restrict__ bn1_v) {
    int b = blockIdx.x;
    __shared__ float xs[EDIM];
    __shared__ float ks[OCFW];
    __shared__ float sc[32], sh[32];
    int t = threadIdx.x; // 192
    for (int j = t; j < EDIM; j += 192) xs[j] = g_x[b * EDIM + j];
    for (int j = t; j < OCFW; j += 192) ks[j] = g_k[b * OCFW + j];
    if (t < 32) {
        float s = bn1_g[t] * rsqrtf(bn1_v[t] + EPS);
        sc[t] = s;
        sh[t] = bn1_b[t] - bn1_m[t] * s;
    }
    __syncthreads();
    int p = t;
    float xv[9];
#pragma unroll
    for (int w = 0; w < 9; w++) xv[w] = xs[p + w];
    __nv_bfloat16* outrow = &g_flat_bf[(size_t)b * FCIN];
#pragma unroll 4
    for (int oc = 0; oc < 32; oc++) {
        float s = 0.f;
#pragma unroll
        for (int w = 0; w < 9; w++) s += xv[w] * ks[oc * 9 + w];
        outrow[oc * 192 + p] = __float2bfloat16(s * sc[oc] + sh[oc]);
    }
}

// ---------------- split-K reduce + fc bias + bn2 + relu -> bf16 h ---------------
// evict-first reads of the 13MB read-once partials: protect L2 for g_ent_bf
__global__ void reduce_kernel(const float* __restrict__ fc_b,
                              const float* __restrict__ g2,
                              const float* __restrict__ b2,
                              const float* __restrict__ m2,
                              const float* __restrict__ v2) {
    int b = blockIdx.x;
    int n = threadIdx.x;       // 208
    float r = 0.f;
    if (n < EDIM) {
        float s = fc_b[n];
        int idx = b * EDIM + n;
#pragma unroll
        for (int z = 0; z < SPLITK; z++)
            s += ld_cs_f(g_part + (size_t)z * BSZ * EDIM + idx);
        float sc = g2[n] * rsqrtf(v2[n] + EPS);
        s = (s - m2[n]) * sc + b2[n];
        r = fmaxf(s, 0.f);
    }
    g_h_bf[b * KP4 + n] = __float2bfloat16(r);
}

// ---------------- launch -------------------------------------------------------
extern "C" void kernel_launch(void* const* d_in, const int* in_sizes, int n_in,
                              void* d_out, int out_size) {
    const int*   e_s    = (const int*)d_in[0];
    const int*   q_s    = (const int*)d_in[1];
    const int*   e_c    = (const int*)d_in[2];
    const float* ent    = (const float*)d_in[3];
    const float* rel    = (const float*)d_in[4];
    const float* W1_w   = (const float*)d_in[5];
    const float* W1_b   = (const float*)d_in[6];
    const float* fc1_w  = (const float*)d_in[7];
    const float* fc1_b  = (const float*)d_in[8];
    const float* fc_w   = (const float*)d_in[9];
    const float* fc_b   = (const float*)d_in[10];
    const float* bn0_g  = (const float*)d_in[11];
    const float* bn0_b  = (const float*)d_in[12];
    const float* bn0_m  = (const float*)d_in[13];
    const float* bn0_v  = (const float*)d_in[14];
    const float* bn1_g  = (const float*)d_in[15];
    const float* bn1_b  = (const float*)d_in[16];
    const float* bn1_m  = (const float*)d_in[17];
    const float* bn1_v  = (const float*)d_in[18];
    const float* bn2_g  = (const float*)d_in[19];
    const float* bn2_b  = (const float*)d_in[20];
    const float* bn2_m  = (const float*)d_in[21];
    const float* bn2_v  = (const float*)d_in[22];
    const float* bias_b = (const float*)d_in[23];
    float* out = (float*)d_out;

    cudaFuncSetAttribute(gemm23_kernel, cudaFuncAttributeMaxDynamicSharedMemorySize, SMEM_TC);
    cudaFuncSetAttribute(gemm5_kernel,  cudaFuncAttributeMaxDynamicSharedMemorySize, SMEM_TC);
    cudaFuncSetAttribute(gemm4_ms,      cudaFuncAttributeMaxDynamicSharedMemorySize, SM4_TOTAL);

    // 1) all converters + gather, one launch (R8)
    prep_kernel<<<NB_PREP, 256>>>(ent, rel, W1_w, fc1_w, fc_w, e_s, q_s, e_c);

    // 2) GEMM2 + GEMM3, one launch (R8)
    {
        dim3 g(5, 8, 1);
        gemm23_kernel<<<g, 256, SMEM_TC>>>(W1_b, bn0_g, bn0_v, bn0_m, bn0_b, fc1_b);
    }

    // 3) per-sample conv + bn1 -> g_flat_bf (R8)
    conv_kernel<<<BSZ, 192>>>(bn1_g, bn1_b, bn1_m, bn1_v);

    // 4) split-K partials of flat @ fc_w (16-way)
    {
        dim3 g(2, 8, SPLITK);
        gemm5_kernel<<<g, 256, SMEM_TC>>>();
    }

    // 5) reduce + fc_b + bn2 + relu -> g_h_bf (evict-first partial reads)
    reduce_kernel<<<BSZ, KP4>>>(fc_b, bn2_g, bn2_b, bn2_m, bn2_v);

    // 6) logits = h @ ent^T + bias_b, sigmoid -> out
    //    grid transposed: x = m-stripes (fast), y = n-tiles
    {
        dim3 g(8, (NE_ + 127) / 128, 1);
        gemm4_ms<<<g, 256, SM4_TOTAL>>>(bias_b, out);
    }
}

// round 16
// speedup vs baseline: 1.0255x; 1.0255x over previous
#include <cuda_runtime.h>
#include <cuda_bf16.h>
#include <math.h>
#include <cstdint>

#define EPS 1e-5f

// Problem dims
#define BSZ   1024
#define EDIM  200
#define NE_   50000
#define OCFW  288     // 32*9
#define FCIN  6144    // 32*192
#define SPLITK 16

#define KP2   416     // K pad for GEMM2 (E+R=400 -> 13*32)
#define KPS   224     // K pad for 200-dim mma.sync operands (7*32)
#define KP4   208     // K pad for GEMM4 operands (13*16)
#define LDS_  40      // smem row stride bf16 (80B) - conflict-free ldmatrix
#define STAGE_BYTES (2 * 128 * LDS_ * 2)   // A+B per stage = 20480
#define SMEM_TC (3 * STAGE_BYTES)          // 61440

// GEMM4 (A-resident, 128x128 CTA tile) smem layout, 3 B stages (R12-proven)
#define A4_STR 232
#define SM4A   (128 * A4_STR * 2)           // 59392
#define SM4B_STAGE (128 * LDS_ * 2)         // 10240
#define SM4_TOTAL (SM4A + 3 * SM4B_STAGE)   // 90112

// prep kernel block ranges (R8-proven all-in-one)
#define NB_ENT    ((NE_ * 52 + 255) / 256)          // 10157
#define NB_W1T    ((EDIM * KP2 + 255) / 256)        // 325
#define NB_FC1T   ((OCFW * KPS + 255) / 256)        // 252
#define NB_FCT    ((FCIN / 32) * ((EDIM + 31) / 32))// 1344
#define NB_GATHER BSZ
#define OFF_W1T    NB_ENT
#define OFF_FC1T   (OFF_W1T + NB_W1T)
#define OFF_FCT    (OFF_FC1T + NB_FC1T)
#define OFF_GATHER (OFF_FCT + NB_FCT)
#define NB_PREP    (OFF_GATHER + NB_GATHER)

typedef unsigned unt;

// ---------------- scratch ----------------------------------------------------
__device__ __align__(16) __nv_bfloat16 g_cat_bf [BSZ * KP2];
__device__ __align__(16) __nv_bfloat16 g_rg_bf  [BSZ * KPS];
__device__ float g_x   [BSZ * EDIM];
__device__ float g_k   [BSZ * OCFW];
__device__ __align__(16) __nv_bfloat16 g_flat_bf[BSZ * FCIN];
__device__ float g_part[SPLITK * BSZ * EDIM];
__device__ __align__(16) __nv_bfloat16 g_h_bf [BSZ * KP4];
__device__ __align__(16) __nv_bfloat16 g_ent_bf[(size_t)NE_ * KP4];  // 20.8MB
__device__ __align__(16) __nv_bfloat16 g_w1t [EDIM * KP2];
__device__ __align__(16) __nv_bfloat16 g_fc1t[OCFW * KPS];
__device__ __align__(16) __nv_bfloat16 g_fct [EDIM * FCIN];

// ---------------- asm helpers --------------------------------------------------
__device__ __forceinline__ unt smem_u32(const void* p) {
    unt a;
    asm("{ .reg .u64 t; cvta.to.shared.u64 t, %1; cvt.u32.u64 %0, t; }"
        : "=r"(a) : "l"(p));
    return a;
}
__device__ __forceinline__ void ldsm_x4(unt* r, const __nv_bfloat16* p) {
    unt addr = smem_u32(p);
    asm volatile("ldmatrix.sync.aligned.m8n8.x4.shared.b16 {%0,%1,%2,%3}, [%4];"
                 : "=r"(r[0]), "=r"(r[1]), "=r"(r[2]), "=r"(r[3]) : "r"(addr));
}
__device__ __forceinline__ void mma_bf16(float* c, const unt* a, const unt* b) {
    asm volatile("mma.sync.aligned.m16n8k16.row.col.f32.bf16.bf16.f32 "
                 "{%0,%1,%2,%3},{%4,%5,%6,%7},{%8,%9},{%0,%1,%2,%3};"
                 : "+f"(c[0]), "+f"(c[1]), "+f"(c[2]), "+f"(c[3])
                 : "r"(a[0]), "r"(a[1]), "r"(a[2]), "r"(a[3]),
                   "r"(b[0]), "r"(b[1]));
}
__device__ __forceinline__ void cp16p(__nv_bfloat16* dst, const __nv_bfloat16* src, bool pred) {
    unt d = smem_u32(dst);
    int sz = pred ? 16 : 0;
    asm volatile("cp.async.cg.shared.global [%0], [%1], 16, %2;"
                 :: "r"(d), "l"(src), "r"(sz));
}
#define CP_COMMIT() asm volatile("cp.async.commit_group;")
#define CP_WAIT1()  asm volatile("cp.async.wait_group 1;")

// streaming (evict-first) 8B store: keeps L2 for the entity table
__device__ __forceinline__ void st_cs_f2(float* p, float x, float y) {
    float2 v = make_float2(x, y);
    asm volatile("st.global.cs.v2.f32 [%0], {%1, %2};"
                 :: "l"(p), "f"(v.x), "f"(v.y) : "memory");
}
// streaming (evict-first) load
__device__ __forceinline__ float ld_cs_f(const float* p) {
    float v;
    asm volatile("ld.global.cs.f32 %0, [%1];" : "=f"(v) : "l"(p));
    return v;
}

__device__ __forceinline__ float sigf(float x) {
    float e, r;
    asm("ex2.approx.f32 %0, %1;" : "=f"(e) : "f"(-1.44269504f * x));
    asm("rcp.approx.f32 %0, %1;" : "=f"(r) : "f"(1.f + e));
    return r;
}

// ---------------- prep: all converters + gather in one launch (R8) --------------
__global__ __launch_bounds__(256)
void prep_kernel(const float* __restrict__ ent, const float* __restrict__ rel,
                 const float* __restrict__ W1_w, const float* __restrict__ fc1_w,
                 const float* __restrict__ fc_w,
                 const int* __restrict__ e_s, const int* __restrict__ q_s,
                 const int* __restrict__ e_c) {
    __shared__ float tile[32][33];
    const int bid = blockIdx.x;
    const int t = threadIdx.x;

    if (bid < NB_ENT) {
        int idx = bid * 256 + t;
        if (idx < NE_ * 52) {
            int r = idx / 52, q = idx % 52;
            float4 v = make_float4(0.f, 0.f, 0.f, 0.f);
            if (q < 50) v = *(const float4*)(ent + (size_t)r * EDIM + q * 4);
            __nv_bfloat162 lo = __floats2bfloat162_rn(v.x, v.y);
            __nv_bfloat162 hi = __floats2bfloat162_rn(v.z, v.w);
            uint2 pk;
            pk.x = *(unt*)&lo; pk.y = *(unt*)&hi;
            *(uint2*)(g_ent_bf + (size_t)r * KP4 + q * 4) = pk;
        }
    } else if (bid < OFF_FC1T) {
        int idx = (bid - OFF_W1T) * 256 + t;
        if (idx < EDIM * KP2) {
            int n = idx / KP2, c = idx % KP2;
            float v = (c < 2 * EDIM) ? W1_w[c * EDIM + n] : 0.f;
            g_w1t[idx] = __float2bfloat16(v);
        }
    } else if (bid < OFF_FCT) {
        int idx = (bid - OFF_FC1T) * 256 + t;
        if (idx < OCFW * KPS) {
            int n = idx / KPS, c = idx % KPS;
            float v = (c < EDIM) ? fc1_w[c * OCFW + n] : 0.f;
            g_fc1t[idx] = __float2bfloat16(v);
        }
    } else if (bid < OFF_GATHER) {
        int b2 = bid - OFF_FCT;
        int bx = b2 % (FCIN / 32);
        int by = b2 / (FCIN / 32);
        int tx = t & 31, ty = t >> 5;
        int cbase = bx * 32;
        int nbase = by * 32;
#pragma unroll
        for (int j = 0; j < 4; j++) {
            int cc = cbase + ty + j * 8;
            int nn = nbase + tx;
            tile[ty + j * 8][tx] = (nn < EDIM) ? fc_w[(size_t)cc * EDIM + nn] : 0.f;
        }
        __syncthreads();
#pragma unroll
        for (int j = 0; j < 4; j++) {
            int nn = nbase + ty + j * 8;
            int cc = cbase + tx;
            if (nn < EDIM)
                g_fct[(size_t)nn * FCIN + cc] = __float2bfloat16(tile[tx][ty + j * 8]);
        }
    } else {
        int b = bid - OFF_GATHER;
        int s = e_s[b], c = e_c[b], q = q_s[b];
        for (int j = t; j < KP2; j += 256) {
            float cv = 0.f;
            if (j < EDIM)          cv = ent[(size_t)s * EDIM + j];
            else if (j < 2 * EDIM) cv = ent[(size_t)c * EDIM + (j - EDIM)];
            g_cat_bf[b * KP2 + j] = __float2bfloat16(cv);
        }
        for (int j = t; j < KPS; j += 256) {
            float rv = (j < EDIM) ? rel[(size_t)q * EDIM + j] : 0.f;
            g_rg_bf[b * KPS + j] = __float2bfloat16(rv);
        }
    }
}

// ---------------- shared mma.sync GEMM body (runtime mode) ---------------------
__device__ __forceinline__ void gemm_body(
    int mode, const __nv_bfloat16* A, const __nv_bfloat16* B, float* C,
    int N, int kp, int kiters, int ksteps, int ldc,
    const float* bias, const float* p0, const float* p1,
    const float* p2, const float* p3,
    int m0, int n0, int kbase, size_t rowbase, char* sm) {
    const int tid = threadIdx.x;

    auto load_stage = [&](int kb, int stage) {
        __nv_bfloat16* As = (__nv_bfloat16*)(sm + stage * STAGE_BYTES);
        __nv_bfloat16* Bs = As + 128 * LDS_;
#pragma unroll
        for (int j = 0; j < 2; j++) {
            int i = tid + j * 256;
            int r = i >> 2, c = (i & 3) * 8;
            cp16p(As + r * LDS_ + c, A + (size_t)(m0 + r) * kp + kb * 32 + c, true);
            bool pn = (n0 + r) < N;
            const __nv_bfloat16* bs = pn ? (B + (size_t)(n0 + r) * kp + kb * 32 + c) : B;
            cp16p(Bs + r * LDS_ + c, bs, pn);
        }
    };

    load_stage(kbase + 0, 0); CP_COMMIT();
    load_stage(kbase + 1, 1); CP_COMMIT();

    const int lane = tid & 31, wid = tid >> 5;
    const int wm = (wid & 3) * 32;
    const int wn = (wid >> 2) * 64;

    float acc[2][8][4];
#pragma unroll
    for (int i = 0; i < 2; i++)
#pragma unroll
        for (int j = 0; j < 8; j++)
#pragma unroll
            for (int l = 0; l < 4; l++) acc[i][j][l] = 0.f;

    for (int kb = 0; kb < kiters; kb++) {
        CP_WAIT1();
        __syncthreads();
        if (kb + 2 < kiters) load_stage(kbase + kb + 2, (kb + 2) % 3);
        CP_COMMIT();
        int smax = ksteps - 2 * kb;
        if (smax > 2) smax = 2;
        const __nv_bfloat16* As = (const __nv_bfloat16*)(sm + (kb % 3) * STAGE_BYTES);
        const __nv_bfloat16* Bs = As + 128 * LDS_;
#pragma unroll
        for (int ks = 0; ks < 2; ks++) {
            if (ks >= smax) break;
            unt a[2][4];
#pragma unroll
            for (int mi = 0; mi < 2; mi++) {
                int row = wm + mi * 16 + (lane & 15);
                ldsm_x4(a[mi], As + row * LDS_ + ks * 16 + (lane >> 4) * 8);
            }
            unt b[8][2];
#pragma unroll
            for (int nj = 0; nj < 4; nj++) {
                int row = wn + nj * 16 + ((lane >> 4) & 1) * 8 + (lane & 7);
                int ko  = ks * 16 + ((lane >> 3) & 1) * 8;
                unt tt[4];
                ldsm_x4(tt, Bs + row * LDS_ + ko);
                b[2 * nj][0] = tt[0]; b[2 * nj][1] = tt[1];
                b[2 * nj + 1][0] = tt[2]; b[2 * nj + 1][1] = tt[3];
            }
#pragma unroll
            for (int mi = 0; mi < 2; mi++)
#pragma unroll
                for (int ni = 0; ni < 8; ni++)
                    mma_bf16(acc[mi][ni], a[mi], b[ni]);
        }
        __syncthreads();
    }

    float sc0 = 1.f, sm0 = 0.f, sb0 = 0.f;
    if (mode == 0) {
        sc0 = p0[0] * rsqrtf(p1[0] + EPS);
        sm0 = p2[0];
        sb0 = p3[0];
    }
#pragma unroll
    for (int mi = 0; mi < 2; mi++) {
#pragma unroll
        for (int ni = 0; ni < 8; ni++) {
            int row = m0 + wm + mi * 16 + (lane >> 2);
            int col = n0 + wn + ni * 8 + (lane & 3) * 2;
            if (col < N) {
                float v0 = acc[mi][ni][0];
                float v1 = acc[mi][ni][1];
                float v2 = acc[mi][ni][2];
                float v3 = acc[mi][ni][3];
                if (mode != 2) {
                    float bb0 = bias[col], bb1 = bias[col + 1];
                    v0 += bb0; v1 += bb1; v2 += bb0; v3 += bb1;
                }
                if (mode == 0) {
                    v0 = (v0 - sm0) * sc0 + sb0; v1 = (v1 - sm0) * sc0 + sb0;
                    v2 = (v2 - sm0) * sc0 + sb0; v3 = (v3 - sm0) * sc0 + sb0;
                }
                if (mode == 2) {
                    st_cs_f2(C + (rowbase + row) * (size_t)ldc + col,     v0, v1);
                    st_cs_f2(C + (rowbase + row + 8) * (size_t)ldc + col, v2, v3);
                } else {
                    *(float2*)(C + (rowbase + row) * (size_t)ldc + col)     = make_float2(v0, v1);
                    *(float2*)(C + (rowbase + row + 8) * (size_t)ldc + col) = make_float2(v2, v3);
                }
            }
        }
    }
}

// ---------------- GEMM2 + GEMM3 fused into one launch (R8) ----------------------
__global__ __launch_bounds__(256, 2)
void gemm23_kernel(const float* __restrict__ W1_b,
                   const float* __restrict__ bn0_g, const float* __restrict__ bn0_v,
                   const float* __restrict__ bn0_m, const float* __restrict__ bn0_b,
                   const float* __restrict__ fc1_b) {
    extern __shared__ char sm[];
    const int bx = blockIdx.x;
    const int m0 = blockIdx.y * 128;
    if (bx < 2) {
        gemm_body(0, g_cat_bf, g_w1t, g_x, EDIM, KP2, KP2 / 32, 25, EDIM,
                  W1_b, bn0_g, bn0_v, bn0_m, bn0_b, m0, bx * 128, 0, 0, sm);
    } else {
        gemm_body(1, g_rg_bf, g_fc1t, g_k, OCFW, KPS, KPS / 32, 13, OCFW,
                  fc1_b, nullptr, nullptr, nullptr, nullptr,
                  m0, (bx - 2) * 128, 0, 0, sm);
    }
}

// ---------------- GEMM5: split-K partials (SPLITK=16, measured better) ----------
__global__ __launch_bounds__(256, 2)
void gemm5_kernel() {
    extern __shared__ char sm[];
    const int kiters = FCIN / 32 / SPLITK;   // 12
    gemm_body(2, g_flat_bf, g_fct, g_part, EDIM, FCIN, kiters, 2 * kiters, EDIM,
              nullptr, nullptr, nullptr, nullptr, nullptr,
              blockIdx.y * 128, blockIdx.x * 128, blockIdx.z * kiters,
              (size_t)blockIdx.z * BSZ, sm);
}

// ---------------- GEMM4: 128x128 CTA tile, A-resident, 3-stage B (R14) ----------
__global__ __launch_bounds__(256, 2)
void gemm4_ms(const float* __restrict__ bias, float* __restrict__ out) {
    extern __shared__ char sm[];
    __nv_bfloat16* Asm = (__nv_bfloat16*)sm;
    const int tid = threadIdx.x;
    const int m0 = blockIdx.y * 128;
    const int n0 = blockIdx.x * 128;

    for (int i = tid; i < 3328; i += 256) {
        int r = i / 26, c = (i % 26) * 8;
        cp16p(Asm + r * A4_STR + c, g_h_bf + (size_t)(m0 + r) * KP4 + c, true);
    }
    CP_COMMIT();

    auto loadB = [&](int kb, int st) {
        __nv_bfloat16* Bs = (__nv_bfloat16*)(sm + SM4A + st * SM4B_STAGE);
#pragma unroll
        for (int j = 0; j < 2; j++) {
            int i = tid + j * 256;
            int r = i >> 2, c = (i & 3) * 8;
            bool pv = ((n0 + r) < NE_) && (kb * 32 + c < KP4);
            const __nv_bfloat16* src =
                pv ? (g_ent_bf + (size_t)(n0 + r) * KP4 + kb * 32 + c) : g_ent_bf;
            cp16p(Bs + r * LDS_ + c, src, pv);
        }
    };
    loadB(0, 0); CP_COMMIT();
    loadB(1, 1); CP_COMMIT();

    const int lane = tid & 31, wid = tid >> 5;
    const int wm = (wid & 3) * 32;
    const int wn = (wid >> 2) * 64;

    float acc[2][8][4];
#pragma unroll
    for (int i = 0; i < 2; i++)
#pragma unroll
        for (int j = 0; j < 8; j++)
#pragma unroll
            for (int l = 0; l < 4; l++) acc[i][j][l] = 0.f;

#pragma unroll
    for (int kb = 0; kb < 7; kb++) {
        CP_WAIT1();
        __syncthreads();
        if (kb + 2 < 7) loadB(kb + 2, (kb + 2) % 3);
        CP_COMMIT();
        const __nv_bfloat16* Bs =
            (const __nv_bfloat16*)(sm + SM4A + (kb % 3) * SM4B_STAGE);
        int smax = (kb == 6) ? 1 : 2;     // k 208..224 is pad
#pragma unroll
        for (int ks = 0; ks < 2; ks++) {
            if (ks >= smax) break;
            unt a[2][4];
#pragma unroll
            for (int mi = 0; mi < 2; mi++) {
                int row = wm + mi * 16 + (lane & 15);
                ldsm_x4(a[mi], Asm + row * A4_STR + kb * 32 + ks * 16 + (lane >> 4) * 8);
            }
            unt b[8][2];
#pragma unroll
            for (int nj = 0; nj < 4; nj++) {
                int row = wn + nj * 16 + ((lane >> 4) & 1) * 8 + (lane & 7);
                int ko  = ks * 16 + ((lane >> 3) & 1) * 8;
                unt tt[4];
                ldsm_x4(tt, Bs + row * LDS_ + ko);
                b[2 * nj][0] = tt[0]; b[2 * nj][1] = tt[1];
                b[2 * nj + 1][0] = tt[2]; b[2 * nj + 1][1] = tt[3];
            }
#pragma unroll
            for (int mi = 0; mi < 2; mi++)
#pragma unroll
                for (int ni = 0; ni < 8; ni++)
                    mma_bf16(acc[mi][ni], a[mi], b[ni]);
        }
        __syncthreads();
    }

    // epilogue: + bias, sigmoid; STREAMING stores (keep entity table in L2)
#pragma unroll
    for (int mi = 0; mi < 2; mi++) {
#pragma unroll
        for (int ni = 0; ni < 8; ni++) {
            int row = m0 + wm + mi * 16 + (lane >> 2);
            int col = n0 + wn + ni * 8 + (lane & 3) * 2;
            if (col < NE_) {
                float bb0 = bias[col], bb1 = bias[col + 1];
                float v0 = sigf(acc[mi][ni][0] + bb0);
                float v1 = sigf(acc[mi][ni][1] + bb1);
                float v2 = sigf(acc[mi][ni][2] + bb0);
                float v3 = sigf(acc[mi][ni][3] + bb1);
                st_cs_f2(out + (size_t)row * NE_ + col,       v0, v1);
                st_cs_f2(out + (size_t)(row + 8) * NE_ + col, v2, v3);
            }
        }
    }
}

// ---------------- per-sample dynamic conv + bn1 -> bf16 flat (R8, 192 thr) ------
__global__ void conv_kernel(const float* __restrict__ bn1_g,
                            const float* __restrict__ bn1_b,
                            const float* __restrict__ bn1_m,
                            const float* __restrict__ bn1_v) {
    int b = blockIdx.x;
    __shared__ float xs[EDIM];
    __shared__ float ks[OCFW];
    __shared__ float sc[32], sh[32];
    int t = threadIdx.x; // 192
    for (int j = t; j < EDIM; j += 192) xs[j] = g_x[b * EDIM + j];
    for (int j = t; j < OCFW; j += 192) ks[j] = g_k[b * OCFW + j];
    if (t < 32) {
        float s = bn1_g[t] * rsqrtf(bn1_v[t] + EPS);
        sc[t] = s;
        sh[t] = bn1_b[t] - bn1_m[t] * s;
    }
    __syncthreads();
    int p = t;
    float xv[9];
#pragma unroll
    for (int w = 0; w < 9; w++) xv[w] = xs[p + w];
    __nv_bfloat16* outrow = &g_flat_bf[(size_t)b * FCIN];
#pragma unroll 4
    for (int oc = 0; oc < 32; oc++) {
        float s = 0.f;
#pragma unroll
        for (int w = 0; w < 9; w++) s += xv[w] * ks[oc * 9 + w];
        outrow[oc * 192 + p] = __float2bfloat16(s * sc[oc] + sh[oc]);
    }
}

// ---------------- split-K reduce + fc bias + bn2 + relu -> bf16 h ---------------
// evict-first reads of the 13MB read-once partials: protect L2 for g_ent_bf
__global__ void reduce_kernel(const float* __restrict__ fc_b,
                              const float* __restrict__ g2,
                              const float* __restrict__ b2,
                              const float* __restrict__ m2,
                              const float* __restrict__ v2) {
    int b = blockIdx.x;
    int n = threadIdx.x;       // 208
    float r = 0.f;
    if (n < EDIM) {
        float s = fc_b[n];
        int idx = b * EDIM + n;
#pragma unroll
        for (int z = 0; z < SPLITK; z++)
            s += ld_cs_f(g_part + (size_t)z * BSZ * EDIM + idx);
        float sc = g2[n] * rsqrtf(v2[n] + EPS);
        s = (s - m2[n]) * sc + b2[n];
        r = fmaxf(s, 0.f);
    }
    g_h_bf[b * KP4 + n] = __float2bfloat16(r);
}

// ---------------- launch -------------------------------------------------------
extern "C" void kernel_launch(void* const* d_in, const int* in_sizes, int n_in,
                              void* d_out, int out_size) {
    const int*   e_s    = (const int*)d_in[0];
    const int*   q_s    = (const int*)d_in[1];
    const int*   e_c    = (const int*)d_in[2];
    const float* ent    = (const float*)d_in[3];
    const float* rel    = (const float*)d_in[4];
    const float* W1_w   = (const float*)d_in[5];
    const float* W1_b   = (const float*)d_in[6];
    const float* fc1_w  = (const float*)d_in[7];
    const float* fc1_b  = (const float*)d_in[8];
    const float* fc_w   = (const float*)d_in[9];
    const float* fc_b   = (const float*)d_in[10];
    const float* bn0_g  = (const float*)d_in[11];
    const float* bn0_b  = (const float*)d_in[12];
    const float* bn0_m  = (const float*)d_in[13];
    const float* bn0_v  = (const float*)d_in[14];
    const float* bn1_g  = (const float*)d_in[15];
    const float* bn1_b  = (const float*)d_in[16];
    const float* bn1_m  = (const float*)d_in[17];
    const float* bn1_v  = (const float*)d_in[18];
    const float* bn2_g  = (const float*)d_in[19];
    const float* bn2_b  = (const float*)d_in[20];
    const float* bn2_m  = (const float*)d_in[21];
    const float* bn2_v  = (const float*)d_in[22];
    const float* bias_b = (const float*)d_in[23];
    float* out = (float*)d_out;

    cudaFuncSetAttribute(gemm23_kernel, cudaFuncAttributeMaxDynamicSharedMemorySize, SMEM_TC);
    cudaFuncSetAttribute(gemm5_kernel,  cudaFuncAttributeMaxDynamicSharedMemorySize, SMEM_TC);
    cudaFuncSetAttribute(gemm4_ms,      cudaFuncAttributeMaxDynamicSharedMemorySize, SM4_TOTAL);

    // 1) all converters + gather, one launch (R8)
    prep_kernel<<<NB_PREP, 256>>>(ent, rel, W1_w, fc1_w, fc_w, e_s, q_s, e_c);

    // 2) GEMM2 + GEMM3, one launch (R8)
    {
        dim3 g(5, 8, 1);
        gemm23_kernel<<<g, 256, SMEM_TC>>>(W1_b, bn0_g, bn0_v, bn0_m, bn0_b, fc1_b);
    }

    // 3) per-sample conv + bn1 -> g_flat_bf (R8)
    conv_kernel<<<BSZ, 192>>>(bn1_g, bn1_b, bn1_m, bn1_v);

    // 4) split-K partials of flat @ fc_w (16-way)
    {
        dim3 g(2, 8, SPLITK);
        gemm5_kernel<<<g, 256, SMEM_TC>>>();
    }

    // 5) reduce + fc_b + bn2 + relu -> g_h_bf (evict-first partial reads)
    reduce_kernel<<<BSZ, KP4>>>(fc_b, bn2_g, bn2_b, bn2_m, bn2_v);

    // 6) logits = h @ ent^T + bias_b, sigmoid -> out (R14: n-tiles fastest)
    {
        dim3 g((NE_ + 127) / 128, 8, 1);
        gemm4_ms<<<g, 256, SM4_TOTAL>>>(bias_b, out);
    }
}

// round 17
// speedup vs baseline: 1.0398x; 1.0139x over previous
#include <cuda_runtime.h>
#include <cuda_bf16.h>
#include <math.h>
#include <cstdint>

#define EPS 1e-5f

// Problem dims
#define BSZ   1024
#define EDIM  200
#define NE_   50000
#define OCFW  288     // 32*9
#define FCIN  6144    // 32*192
#define SPLITK 16

#define KP2   416     // K pad for GEMM2 (E+R=400 -> 13*32)
#define KPS   224     // K pad for 200-dim mma.sync operands (7*32)
#define KP4   208     // K pad for GEMM4 operands (13*16)
#define LDS_  40      // smem row stride bf16 (80B) - conflict-free ldmatrix
#define STAGE_BYTES (2 * 128 * LDS_ * 2)   // A+B per stage = 20480
#define SMEM_TC (3 * STAGE_BYTES)          // 61440

// GEMM4 (A-resident, 128x128 CTA tile) smem layout, 3 B stages (R12-proven)
#define A4_STR 232
#define SM4A   (128 * A4_STR * 2)           // 59392
#define SM4B_STAGE (128 * LDS_ * 2)         // 10240
#define SM4_TOTAL (SM4A + 3 * SM4B_STAGE)   // 90112

// prep kernel block ranges (R8-proven all-in-one)
#define NB_ENT    ((NE_ * 52 + 255) / 256)          // 10157
#define NB_W1T    ((EDIM * KP2 + 255) / 256)        // 325
#define NB_FC1T   ((OCFW * KPS + 255) / 256)        // 252
#define NB_FCT    ((FCIN / 32) * ((EDIM + 31) / 32))// 1344
#define NB_GATHER BSZ
#define OFF_W1T    NB_ENT
#define OFF_FC1T   (OFF_W1T + NB_W1T)
#define OFF_FCT    (OFF_FC1T + NB_FC1T)
#define OFF_GATHER (OFF_FCT + NB_FCT)
#define NB_PREP    (OFF_GATHER + NB_GATHER)

typedef unsigned unt;

// ---------------- scratch ----------------------------------------------------
__device__ __align__(16) __nv_bfloat16 g_cat_bf [BSZ * KP2];
__device__ __align__(16) __nv_bfloat16 g_rg_bf  [BSZ * KPS];
__device__ float g_x   [BSZ * EDIM];
__device__ float g_k   [BSZ * OCFW];
__device__ __align__(16) __nv_bfloat16 g_flat_bf[BSZ * FCIN];
__device__ float g_part[SPLITK * BSZ * EDIM];
__device__ __align__(16) __nv_bfloat16 g_h_bf [BSZ * KP4];
__device__ __align__(16) __nv_bfloat16 g_ent_bf[(size_t)NE_ * KP4];  // 20.8MB
__device__ __align__(16) __nv_bfloat16 g_w1t [EDIM * KP2];
__device__ __align__(16) __nv_bfloat16 g_fc1t[OCFW * KPS];
__device__ __align__(16) __nv_bfloat16 g_fct [EDIM * FCIN];

// ---------------- asm helpers --------------------------------------------------
__device__ __forceinline__ unt smem_u32(const void* p) {
    unt a;
    asm("{ .reg .u64 t; cvta.to.shared.u64 t, %1; cvt.u32.u64 %0, t; }"
        : "=r"(a) : "l"(p));
    return a;
}
__device__ __forceinline__ void ldsm_x4(unt* r, const __nv_bfloat16* p) {
    unt addr = smem_u32(p);
    asm volatile("ldmatrix.sync.aligned.m8n8.x4.shared.b16 {%0,%1,%2,%3}, [%4];"
                 : "=r"(r[0]), "=r"(r[1]), "=r"(r[2]), "=r"(r[3]) : "r"(addr));
}
__device__ __forceinline__ void mma_bf16(float* c, const unt* a, const unt* b) {
    asm volatile("mma.sync.aligned.m16n8k16.row.col.f32.bf16.bf16.f32 "
                 "{%0,%1,%2,%3},{%4,%5,%6,%7},{%8,%9},{%0,%1,%2,%3};"
                 : "+f"(c[0]), "+f"(c[1]), "+f"(c[2]), "+f"(c[3])
                 : "r"(a[0]), "r"(a[1]), "r"(a[2]), "r"(a[3]),
                   "r"(b[0]), "r"(b[1]));
}
__device__ __forceinline__ void cp16p(__nv_bfloat16* dst, const __nv_bfloat16* src, bool pred) {
    unt d = smem_u32(dst);
    int sz = pred ? 16 : 0;
    asm volatile("cp.async.cg.shared.global [%0], [%1], 16, %2;"
                 :: "r"(d), "l"(src), "r"(sz));
}
#define CP_COMMIT() asm volatile("cp.async.commit_group;")
#define CP_WAIT1()  asm volatile("cp.async.wait_group 1;")

// streaming (evict-first) 8B store: keeps L2 for the entity table
__device__ __forceinline__ void st_cs_f2(float* p, float x, float y) {
    float2 v = make_float2(x, y);
    asm volatile("st.global.cs.v2.f32 [%0], {%1, %2};"
                 :: "l"(p), "f"(v.x), "f"(v.y) : "memory");
}
// streaming (evict-first) load
__device__ __forceinline__ float ld_cs_f(const float* p) {
    float v;
    asm volatile("ld.global.cs.f32 %0, [%1];" : "=f"(v) : "l"(p));
    return v;
}

__device__ __forceinline__ float sigf(float x) {
    float e, r;
    asm("ex2.approx.f32 %0, %1;" : "=f"(e) : "f"(-1.44269504f * x));
    asm("rcp.approx.f32 %0, %1;" : "=f"(r) : "f"(1.f + e));
    return r;
}

// ---------------- prep: all converters + gather in one launch (R8) --------------
__global__ __launch_bounds__(256)
void prep_kernel(const float* __restrict__ ent, const float* __restrict__ rel,
                 const float* __restrict__ W1_w, const float* __restrict__ fc1_w,
                 const float* __restrict__ fc_w,
                 const int* __restrict__ e_s, const int* __restrict__ q_s,
                 const int* __restrict__ e_c) {
    __shared__ float tile[32][33];
    const int bid = blockIdx.x;
    const int t = threadIdx.x;

    if (bid < NB_ENT) {
        int idx = bid * 256 + t;
        if (idx < NE_ * 52) {
            int r = idx / 52, q = idx % 52;
            float4 v = make_float4(0.f, 0.f, 0.f, 0.f);
            if (q < 50) v = *(const float4*)(ent + (size_t)r * EDIM + q * 4);
            __nv_bfloat162 lo = __floats2bfloat162_rn(v.x, v.y);
            __nv_bfloat162 hi = __floats2bfloat162_rn(v.z, v.w);
            uint2 pk;
            pk.x = *(unt*)&lo; pk.y = *(unt*)&hi;
            *(uint2*)(g_ent_bf + (size_t)r * KP4 + q * 4) = pk;
        }
    } else if (bid < OFF_FC1T) {
        int idx = (bid - OFF_W1T) * 256 + t;
        if (idx < EDIM * KP2) {
            int n = idx / KP2, c = idx % KP2;
            float v = (c < 2 * EDIM) ? W1_w[c * EDIM + n] : 0.f;
            g_w1t[idx] = __float2bfloat16(v);
        }
    } else if (bid < OFF_FCT) {
        int idx = (bid - OFF_FC1T) * 256 + t;
        if (idx < OCFW * KPS) {
            int n = idx / KPS, c = idx % KPS;
            float v = (c < EDIM) ? fc1_w[c * OCFW + n] : 0.f;
            g_fc1t[idx] = __float2bfloat16(v);
        }
    } else if (bid < OFF_GATHER) {
        int b2 = bid - OFF_FCT;
        int bx = b2 % (FCIN / 32);
        int by = b2 / (FCIN / 32);
        int tx = t & 31, ty = t >> 5;
        int cbase = bx * 32;
        int nbase = by * 32;
#pragma unroll
        for (int j = 0; j < 4; j++) {
            int cc = cbase + ty + j * 8;
            int nn = nbase + tx;
            tile[ty + j * 8][tx] = (nn < EDIM) ? fc_w[(size_t)cc * EDIM + nn] : 0.f;
        }
        __syncthreads();
#pragma unroll
        for (int j = 0; j < 4; j++) {
            int nn = nbase + ty + j * 8;
            int cc = cbase + tx;
            if (nn < EDIM)
                g_fct[(size_t)nn * FCIN + cc] = __float2bfloat16(tile[tx][ty + j * 8]);
        }
    } else {
        int b = bid - OFF_GATHER;
        int s = e_s[b], c = e_c[b], q = q_s[b];
        for (int j = t; j < KP2; j += 256) {
            float cv = 0.f;
            if (j < EDIM)          cv = ent[(size_t)s * EDIM + j];
            else if (j < 2 * EDIM) cv = ent[(size_t)c * EDIM + (j - EDIM)];
            g_cat_bf[b * KP2 + j] = __float2bfloat16(cv);
        }
        for (int j = t; j < KPS; j += 256) {
            float rv = (j < EDIM) ? rel[(size_t)q * EDIM + j] : 0.f;
            g_rg_bf[b * KPS + j] = __float2bfloat16(rv);
        }
    }
}

// ---------------- shared mma.sync GEMM body (runtime mode) ---------------------
// single barrier per k-iter: the head barrier (after CP_WAIT1) already orders
// compute(kb-1) reads of slot (kb+2)%3 before loadB(kb+2) overwrites it.
__device__ __forceinline__ void gemm_body(
    int mode, const __nv_bfloat16* A, const __nv_bfloat16* B, float* C,
    int N, int kp, int kiters, int ksteps, int ldc,
    const float* bias, const float* p0, const float* p1,
    const float* p2, const float* p3,
    int m0, int n0, int kbase, size_t rowbase, char* sm) {
    const int tid = threadIdx.x;

    auto load_stage = [&](int kb, int stage) {
        __nv_bfloat16* As = (__nv_bfloat16*)(sm + stage * STAGE_BYTES);
        __nv_bfloat16* Bs = As + 128 * LDS_;
#pragma unroll
        for (int j = 0; j < 2; j++) {
            int i = tid + j * 256;
            int r = i >> 2, c = (i & 3) * 8;
            cp16p(As + r * LDS_ + c, A + (size_t)(m0 + r) * kp + kb * 32 + c, true);
            bool pn = (n0 + r) < N;
            const __nv_bfloat16* bs = pn ? (B + (size_t)(n0 + r) * kp + kb * 32 + c) : B;
            cp16p(Bs + r * LDS_ + c, bs, pn);
        }
    };

    load_stage(kbase + 0, 0); CP_COMMIT();
    load_stage(kbase + 1, 1); CP_COMMIT();

    const int lane = tid & 31, wid = tid >> 5;
    const int wm = (wid & 3) * 32;
    const int wn = (wid >> 2) * 64;

    float acc[2][8][4];
#pragma unroll
    for (int i = 0; i < 2; i++)
#pragma unroll
        for (int j = 0; j < 8; j++)
#pragma unroll
            for (int l = 0; l < 4; l++) acc[i][j][l] = 0.f;

    for (int kb = 0; kb < kiters; kb++) {
        CP_WAIT1();
        __syncthreads();
        if (kb + 2 < kiters) load_stage(kbase + kb + 2, (kb + 2) % 3);
        CP_COMMIT();
        int smax = ksteps - 2 * kb;
        if (smax > 2) smax = 2;
        const __nv_bfloat16* As = (const __nv_bfloat16*)(sm + (kb % 3) * STAGE_BYTES);
        const __nv_bfloat16* Bs = As + 128 * LDS_;
#pragma unroll
        for (int ks = 0; ks < 2; ks++) {
            if (ks >= smax) break;
            unt a[2][4];
#pragma unroll
            for (int mi = 0; mi < 2; mi++) {
                int row = wm + mi * 16 + (lane & 15);
                ldsm_x4(a[mi], As + row * LDS_ + ks * 16 + (lane >> 4) * 8);
            }
            unt b[8][2];
#pragma unroll
            for (int nj = 0; nj < 4; nj++) {
                int row = wn + nj * 16 + ((lane >> 4) & 1) * 8 + (lane & 7);
                int ko  = ks * 16 + ((lane >> 3) & 1) * 8;
                unt tt[4];
                ldsm_x4(tt, Bs + row * LDS_ + ko);
                b[2 * nj][0] = tt[0]; b[2 * nj][1] = tt[1];
                b[2 * nj + 1][0] = tt[2]; b[2 * nj + 1][1] = tt[3];
            }
#pragma unroll
            for (int mi = 0; mi < 2; mi++)
#pragma unroll
                for (int ni = 0; ni < 8; ni++)
                    mma_bf16(acc[mi][ni], a[mi], b[ni]);
        }
        // no trailing barrier: head barrier of next iter provides the ordering
    }

    float sc0 = 1.f, sm0 = 0.f, sb0 = 0.f;
    if (mode == 0) {
        sc0 = p0[0] * rsqrtf(p1[0] + EPS);
        sm0 = p2[0];
        sb0 = p3[0];
    }
#pragma unroll
    for (int mi = 0; mi < 2; mi++) {
#pragma unroll
        for (int ni = 0; ni < 8; ni++) {
            int row = m0 + wm + mi * 16 + (lane >> 2);
            int col = n0 + wn + ni * 8 + (lane & 3) * 2;
            if (col < N) {
                float v0 = acc[mi][ni][0];
                float v1 = acc[mi][ni][1];
                float v2 = acc[mi][ni][2];
                float v3 = acc[mi][ni][3];
                if (mode != 2) {
                    float bb0 = bias[col], bb1 = bias[col + 1];
                    v0 += bb0; v1 += bb1; v2 += bb0; v3 += bb1;
                }
                if (mode == 0) {
                    v0 = (v0 - sm0) * sc0 + sb0; v1 = (v1 - sm0) * sc0 + sb0;
                    v2 = (v2 - sm0) * sc0 + sb0; v3 = (v3 - sm0) * sc0 + sb0;
                }
                if (mode == 2) {
                    st_cs_f2(C + (rowbase + row) * (size_t)ldc + col,     v0, v1);
                    st_cs_f2(C + (rowbase + row + 8) * (size_t)ldc + col, v2, v3);
                } else {
                    *(float2*)(C + (rowbase + row) * (size_t)ldc + col)     = make_float2(v0, v1);
                    *(float2*)(C + (rowbase + row + 8) * (size_t)ldc + col) = make_float2(v2, v3);
                }
            }
        }
    }
}

// ---------------- GEMM2 + GEMM3 fused into one launch (R8) ----------------------
__global__ __launch_bounds__(256, 2)
void gemm23_kernel(const float* __restrict__ W1_b,
                   const float* __restrict__ bn0_g, const float* __restrict__ bn0_v,
                   const float* __restrict__ bn0_m, const float* __restrict__ bn0_b,
                   const float* __restrict__ fc1_b) {
    extern __shared__ char sm[];
    const int bx = blockIdx.x;
    const int m0 = blockIdx.y * 128;
    if (bx < 2) {
        gemm_body(0, g_cat_bf, g_w1t, g_x, EDIM, KP2, KP2 / 32, 25, EDIM,
                  W1_b, bn0_g, bn0_v, bn0_m, bn0_b, m0, bx * 128, 0, 0, sm);
    } else {
        gemm_body(1, g_rg_bf, g_fc1t, g_k, OCFW, KPS, KPS / 32, 13, OCFW,
                  fc1_b, nullptr, nullptr, nullptr, nullptr,
                  m0, (bx - 2) * 128, 0, 0, sm);
    }
}

// ---------------- GEMM5: split-K partials (SPLITK=16, measured better) ----------
__global__ __launch_bounds__(256, 2)
void gemm5_kernel() {
    extern __shared__ char sm[];
    const int kiters = FCIN / 32 / SPLITK;   // 12
    gemm_body(2, g_flat_bf, g_fct, g_part, EDIM, FCIN, kiters, 2 * kiters, EDIM,
              nullptr, nullptr, nullptr, nullptr, nullptr,
              blockIdx.y * 128, blockIdx.x * 128, blockIdx.z * kiters,
              (size_t)blockIdx.z * BSZ, sm);
}

// ---------------- GEMM4: 128x128 CTA tile, A-resident, 3-stage B (R14) ----------
__global__ __launch_bounds__(256, 2)
void gemm4_ms(const float* __restrict__ bias, float* __restrict__ out) {
    extern __shared__ char sm[];
    __nv_bfloat16* Asm = (__nv_bfloat16*)sm;
    const int tid = threadIdx.x;
    const int m0 = blockIdx.y * 128;
    const int n0 = blockIdx.x * 128;

    for (int i = tid; i < 3328; i += 256) {
        int r = i / 26, c = (i % 26) * 8;
        cp16p(Asm + r * A4_STR + c, g_h_bf + (size_t)(m0 + r) * KP4 + c, true);
    }
    CP_COMMIT();

    auto loadB = [&](int kb, int st) {
        __nv_bfloat16* Bs = (__nv_bfloat16*)(sm + SM4A + st * SM4B_STAGE);
#pragma unroll
        for (int j = 0; j < 2; j++) {
            int i = tid + j * 256;
            int r = i >> 2, c = (i & 3) * 8;
            bool pv = ((n0 + r) < NE_) && (kb * 32 + c < KP4);
            const __nv_bfloat16* src =
                pv ? (g_ent_bf + (size_t)(n0 + r) * KP4 + kb * 32 + c) : g_ent_bf;
            cp16p(Bs + r * LDS_ + c, src, pv);
        }
    };
    loadB(0, 0); CP_COMMIT();
    loadB(1, 1); CP_COMMIT();

    const int lane = tid & 31, wid = tid >> 5;
    const int wm = (wid & 3) * 32;
    const int wn = (wid >> 2) * 64;

    float acc[2][8][4];
#pragma unroll
    for (int i = 0; i < 2; i++)
#pragma unroll
        for (int j = 0; j < 8; j++)
#pragma unroll
            for (int l = 0; l < 4; l++) acc[i][j][l] = 0.f;

#pragma unroll
    for (int kb = 0; kb < 7; kb++) {
        CP_WAIT1();
        __syncthreads();
        if (kb + 2 < 7) loadB(kb + 2, (kb + 2) % 3);
        CP_COMMIT();
        const __nv_bfloat16* Bs =
            (const __nv_bfloat16*)(sm + SM4A + (kb % 3) * SM4B_STAGE);
        int smax = (kb == 6) ? 1 : 2;     // k 208..224 is pad
#pragma unroll
        for (int ks = 0; ks < 2; ks++) {
            if (ks >= smax) break;
            unt a[2][4];
#pragma unroll
            for (int mi = 0; mi < 2; mi++) {
                int row = wm + mi * 16 + (lane & 15);
                ldsm_x4(a[mi], Asm + row * A4_STR + kb * 32 + ks * 16 + (lane >> 4) * 8);
            }
            unt b[8][2];
#pragma unroll
            for (int nj = 0; nj < 4; nj++) {
                int row = wn + nj * 16 + ((lane >> 4) & 1) * 8 + (lane & 7);
                int ko  = ks * 16 + ((lane >> 3) & 1) * 8;
                unt tt[4];
                ldsm_x4(tt, Bs + row * LDS_ + ko);
                b[2 * nj][0] = tt[0]; b[2 * nj][1] = tt[1];
                b[2 * nj + 1][0] = tt[2]; b[2 * nj + 1][1] = tt[3];
            }
#pragma unroll
            for (int mi = 0; mi < 2; mi++)
#pragma unroll
                for (int ni = 0; ni < 8; ni++)
                    mma_bf16(acc[mi][ni], a[mi], b[ni]);
        }
        // no trailing barrier: head barrier of next iter provides the ordering
    }

    // epilogue: + bias, sigmoid; STREAMING stores (keep entity table in L2)
#pragma unroll
    for (int mi = 0; mi < 2; mi++) {
#pragma unroll
        for (int ni = 0; ni < 8; ni++) {
            int row = m0 + wm + mi * 16 + (lane >> 2);
            int col = n0 + wn + ni * 8 + (lane & 3) * 2;
            if (col < NE_) {
                float bb0 = bias[col], bb1 = bias[col + 1];
                float v0 = sigf(acc[mi][ni][0] + bb0);
                float v1 = sigf(acc[mi][ni][1] + bb1);
                float v2 = sigf(acc[mi][ni][2] + bb0);
                float v3 = sigf(acc[mi][ni][3] + bb1);
                st_cs_f2(out + (size_t)row * NE_ + col,       v0, v1);
                st_cs_f2(out + (size_t)(row + 8) * NE_ + col, v2, v3);
            }
        }
    }
}

// ---------------- per-sample dynamic conv + bn1 -> bf16 flat (R8, 192 thr) ------
__global__ void conv_kernel(const float* __restrict__ bn1_g,
                            const float* __restrict__ bn1_b,
                            const float* __restrict__ bn1_m,
                            const float* __restrict__ bn1_v) {
    int b = blockIdx.x;
    __shared__ float xs[EDIM];
    __shared__ float ks[OCFW];
    __shared__ float sc[32], sh[32];
    int t = threadIdx.x; // 192
    for (int j = t; j < EDIM; j += 192) xs[j] = g_x[b * EDIM + j];
    for (int j = t; j < OCFW; j += 192) ks[j] = g_k[b * OCFW + j];
    if (t < 32) {
        float s = bn1_g[t] * rsqrtf(bn1_v[t] + EPS);
        sc[t] = s;
        sh[t] = bn1_b[t] - bn1_m[t] * s;
    }
    __syncthreads();
    int p = t;
    float xv[9];
#pragma unroll
    for (int w = 0; w < 9; w++) xv[w] = xs[p + w];
    __nv_bfloat16* outrow = &g_flat_bf[(size_t)b * FCIN];
#pragma unroll 4
    for (int oc = 0; oc < 32; oc++) {
        float s = 0.f;
#pragma unroll
        for (int w = 0; w < 9; w++) s += xv[w] * ks[oc * 9 + w];
        outrow[oc * 192 + p] = __float2bfloat16(s * sc[oc] + sh[oc]);
    }
}

// ---------------- split-K reduce + fc bias + bn2 + relu -> bf16 h ---------------
// evict-first reads of the 13MB read-once partials: protect L2 for g_ent_bf
__global__ void reduce_kernel(const float* __restrict__ fc_b,
                              const float* __restrict__ g2,
                              const float* __restrict__ b2,
                              const float* __restrict__ m2,
                              const float* __restrict__ v2) {
    int b = blockIdx.x;
    int n = threadIdx.x;       // 208
    float r = 0.f;
    if (n < EDIM) {
        float s = fc_b[n];
        int idx = b * EDIM + n;
#pragma unroll
        for (int z = 0; z < SPLITK; z++)
            s += ld_cs_f(g_part + (size_t)z * BSZ * EDIM + idx);
        float sc = g2[n] * rsqrtf(v2[n] + EPS);
        s = (s - m2[n]) * sc + b2[n];
        r = fmaxf(s, 0.f);
    }
    g_h_bf[b * KP4 + n] = __float2bfloat16(r);
}

// ---------------- launch -------------------------------------------------------
extern "C" void kernel_launch(void* const* d_in, const int* in_sizes, int n_in,
                              void* d_out, int out_size) {
    const int*   e_s    = (const int*)d_in[0];
    const int*   q_s    = (const int*)d_in[1];
    const int*   e_c    = (const int*)d_in[2];
    const float* ent    = (const float*)d_in[3];
    const float* rel    = (const float*)d_in[4];
    const float* W1_w   = (const float*)d_in[5];
    const float* W1_b   = (const float*)d_in[6];
    const float* fc1_w  = (const float*)d_in[7];
    const float* fc1_b  = (const float*)d_in[8];
    const float* fc_w   = (const float*)d_in[9];
    const float* fc_b   = (const float*)d_in[10];
    const float* bn0_g  = (const float*)d_in[11];
    const float* bn0_b  = (const float*)d_in[12];
    const float* bn0_m  = (const float*)d_in[13];
    const float* bn0_v  = (const float*)d_in[14];
    const float* bn1_g  = (const float*)d_in[15];
    const float* bn1_b  = (const float*)d_in[16];
    const float* bn1_m  = (const float*)d_in[17];
    const float* bn1_v  = (const float*)d_in[18];
    const float* bn2_g  = (const float*)d_in[19];
    const float* bn2_b  = (const float*)d_in[20];
    const float* bn2_m  = (const float*)d_in[21];
    const float* bn2_v  = (const float*)d_in[22];
    const float* bias_b = (const float*)d_in[23];
    float* out = (float*)d_out;

    cudaFuncSetAttribute(gemm23_kernel, cudaFuncAttributeMaxDynamicSharedMemorySize, SMEM_TC);
    cudaFuncSetAttribute(gemm5_kernel,  cudaFuncAttributeMaxDynamicSharedMemorySize, SMEM_TC);
    cudaFuncSetAttribute(gemm4_ms,      cudaFuncAttributeMaxDynamicSharedMemorySize, SM4_TOTAL);

    // 1) all converters + gather, one launch (R8)
    prep_kernel<<<NB_PREP, 256>>>(ent, rel, W1_w, fc1_w, fc_w, e_s, q_s, e_c);

    // 2) GEMM2 + GEMM3, one launch (R8)
    {
        dim3 g(5, 8, 1);
        gemm23_kernel<<<g, 256, SMEM_TC>>>(W1_b, bn0_g, bn0_v, bn0_m, bn0_b, fc1_b);
    }

    // 3) per-sample conv + bn1 -> g_flat_bf (R8)
    conv_kernel<<<BSZ, 192>>>(bn1_g, bn1_b, bn1_m, bn1_v);

    // 4) split-K partials of flat @ fc_w (16-way)
    {
        dim3 g(2, 8, SPLITK);
        gemm5_kernel<<<g, 256, SMEM_TC>>>();
    }

    // 5) reduce + fc_b + bn2 + relu -> g_h_bf (evict-first partial reads)
    reduce_kernel<<<BSZ, KP4>>>(fc_b, bn2_g, bn2_b, bn2_m, bn2_v);

    // 6) logits = h @ ent^T + bias_b, sigmoid -> out (R14: n-tiles fastest)
    {
        dim3 g((NE_ + 127) / 128, 8, 1);
        gemm4_ms<<<g, 256, SM4_TOTAL>>>(bias_b, out);
    }
}